// round 1
// baseline (speedup 1.0000x reference)
#include <cuda_runtime.h>

#define BB 32
#define JJ 256
#define MM 128
#define DD 200
#define MPAD 201
#define NTHREADS 512

// ---------------- persistent transposed weight scratch (device globals) ----------------
// g_wTg:  [k=0..399][4*d+g]  (k<200 -> w_ih, k>=200 -> w_hh), gate-interleaved so a
//         float4 column gives (i,f,g,o) for one channel d.
// g_bg:   [4*d+g] = b_ih + b_hh, same interleaving.
// g_wTfc: [k][d]  = w_fc[d][k]
// g_wTfc1:[k][d]  = w_fc1[d][k], k over concat(x,q) (400)
__device__ __align__(16) float g_wTg[400 * 800];
__device__ __align__(16) float g_bg[800];
__device__ __align__(16) float g_wTfc[200 * 200];
__device__ __align__(16) float g_wTfc1[400 * 200];

__global__ void prep_kernel(const float* __restrict__ w_fc, const float* __restrict__ w_fc1,
                            const float* __restrict__ w_ih, const float* __restrict__ w_hh,
                            const float* __restrict__ b_ih, const float* __restrict__ b_hh)
{
    int stride = gridDim.x * blockDim.x;
    int i0 = blockIdx.x * blockDim.x + threadIdx.x;

    for (int idx = i0; idx < 400 * 800; idx += stride) {
        int k = idx / 800;
        int rem = idx % 800;
        int d = rem >> 2, g = rem & 3;
        int o = g * 200 + d;
        g_wTg[idx] = (k < 200) ? w_ih[o * 200 + k] : w_hh[o * 200 + (k - 200)];
    }
    for (int idx = i0; idx < 800; idx += stride) {
        int d = idx >> 2, g = idx & 3;
        int o = g * 200 + d;
        g_bg[idx] = b_ih[o] + b_hh[o];
    }
    for (int idx = i0; idx < 200 * 200; idx += stride) {
        int k = idx / 200, d = idx % 200;
        g_wTfc[idx] = w_fc[d * 200 + k];
    }
    for (int idx = i0; idx < 400 * 200; idx += stride) {
        int k = idx / 200, d = idx % 200;
        g_wTfc1[idx] = w_fc1[d * 400 + k];
    }
}

__device__ __forceinline__ float sigmoidf_(float v) { return 1.0f / (1.0f + __expf(-v)); }

// ---------------- SMEM layout (floats) ----------------
// mem banks: 2 * 128 * 201            = 51456
// qh  (q[0:200], h[200:400])          @ 51456, 400
// cat (x[0:200], qcopy[200:400])      @ 51856, 400
// att                                 @ 52256, 128
// cvec                                @ 52384, 200
// sv                                  @ 52584, 200
// cosj                                @ 52784, 128
// part (k-split partials, 1600)       @ 52912, 1600
// red                                 @ 54512, 32
// total 54544 floats = 218176 B  (< 227 KB limit)
#define SM_QH   51456
#define SM_CAT  51856
#define SM_ATT  52256
#define SM_CVEC 52384
#define SM_SV   52584
#define SM_COSJ 52784
#define SM_PART 52912
#define SM_RED  54512
#define SM_TOTAL_FLOATS 54544

__global__ void __launch_bounds__(NTHREADS, 1)
speaker_kernel(const float* __restrict__ cosp, const float* __restrict__ bank,
               const float* __restrict__ mem_a, const float* __restrict__ mem_b,
               const float* __restrict__ b_fc, const float* __restrict__ b_fc1,
               float* __restrict__ out)
{
    extern __shared__ float sm[];
    float* smem_mem = sm;
    float* qh   = sm + SM_QH;
    float* cat  = sm + SM_CAT;
    float* att  = sm + SM_ATT;
    float* cvec = sm + SM_CVEC;
    float* sv   = sm + SM_SV;
    float* cosj = sm + SM_COSJ;
    float* part = sm + SM_PART;
    float* red  = sm + SM_RED;

    const int tid = threadIdx.x;
    const int b = blockIdx.x;

    // Load both memory banks into padded SMEM (stride 201 => conflict-free
    // both for row reads (att) and column reads (h, x)).
    for (int idx = tid; idx < MM * DD; idx += NTHREADS) {
        int m = idx / DD, d = idx % DD;
        smem_mem[m * MPAD + d]             = mem_a[b * MM * DD + idx];
        smem_mem[MM * MPAD + m * MPAD + d] = mem_b[b * MM * DD + idx];
    }
    __syncthreads();

    for (int j = 0; j < JJ; ++j) {
        const int flag = j & 1;
        const int slot = j >> 1;
        float* mem = smem_mem + flag * (MM * MPAD);

        // ---- stage cos_j and bank_j (bank into cat[0:200]); reset c ----
        if (tid < MM) cosj[tid] = cosp[(b * JJ + j) * MM + tid];
        if (tid < DD) { cat[tid] = bank[(j * BB + b) * DD + tid]; cvec[tid] = 0.0f; }
        __syncthreads();

        // ---- h init: h[d] = sum_m cos_j[m] * mem[m][d] ----
        if (tid < DD) {
            float acc = 0.f;
            #pragma unroll 8
            for (int m = 0; m < MM; ++m) acc += cosj[m] * mem[m * MPAD + tid];
            qh[DD + tid] = acc;
        }
        // ---- q init partial: q = bank @ w_fc^T + b_fc ; 8 k-splits x 50 float4 cols ----
        if (tid < 400) {
            int ks = tid / 50, c = tid % 50;
            const float4* W4 = reinterpret_cast<const float4*>(g_wTfc);
            float4 acc = make_float4(0.f, 0.f, 0.f, 0.f);
            int k0 = ks * 25;
            #pragma unroll 5
            for (int k = k0; k < k0 + 25; ++k) {
                float v = cat[k];
                float4 w = W4[k * 50 + c];
                acc.x += v * w.x; acc.y += v * w.y; acc.z += v * w.z; acc.w += v * w.w;
            }
            reinterpret_cast<float4*>(part)[ks * 50 + c] = acc;
        }
        __syncthreads();
        if (tid < DD) {
            float acc = b_fc[tid];
            #pragma unroll
            for (int ks = 0; ks < 8; ++ks) acc += part[ks * 200 + tid];
            qh[tid] = acc;          // q for gates
            cat[DD + tid] = acc;    // q copy for fc1 concat
        }
        __syncthreads();

        // ---------------- inner loop P=3 ----------------
        for (int p = 0; p < 3; ++p) {
            // gates partial: gates = [q,h] @ Wg ; 2 k-splits x 200 float4 cols (K=400)
            if (tid < 400) {
                int ks = tid / 200, c = tid % 200;
                const float4* W4 = reinterpret_cast<const float4*>(g_wTg);
                float4 acc = make_float4(0.f, 0.f, 0.f, 0.f);
                int k0 = ks * 200;
                #pragma unroll 8
                for (int k = k0; k < k0 + 200; ++k) {
                    float v = qh[k];
                    float4 w = W4[k * 200 + c];
                    acc.x += v * w.x; acc.y += v * w.y; acc.z += v * w.z; acc.w += v * w.w;
                }
                reinterpret_cast<float4*>(part)[ks * 200 + c] = acc;
            }
            __syncthreads();
            // combine + LSTM elementwise (gate-interleaved: x=i, y=f, z=g, w=o)
            if (tid < DD) {
                float4 p0 = reinterpret_cast<const float4*>(part)[tid];
                float4 p1 = reinterpret_cast<const float4*>(part)[200 + tid];
                float4 bb4 = reinterpret_cast<const float4*>(g_bg)[tid];
                float ig = p0.x + p1.x + bb4.x;
                float fg = p0.y + p1.y + bb4.y;
                float gg = p0.z + p1.z + bb4.z;
                float og = p0.w + p1.w + bb4.w;
                float cc = sigmoidf_(fg) * cvec[tid] + sigmoidf_(ig) * tanhf(gg);
                cvec[tid] = cc;
                qh[DD + tid] = sigmoidf_(og) * tanhf(cc);
            }
            __syncthreads();
            // attention logits: att[m] = sum_d h[d] * mem[m][d]
            if (tid < MM) {
                float acc = 0.f;
                #pragma unroll 8
                for (int d = 0; d < DD; ++d) acc += qh[DD + d] * mem[tid * MPAD + d];
                att[tid] = acc;
            }
            __syncthreads();
            if (tid < 32) {
                float v = fmaxf(fmaxf(att[tid], att[tid + 32]), fmaxf(att[tid + 64], att[tid + 96]));
                #pragma unroll
                for (int off = 16; off > 0; off >>= 1) v = fmaxf(v, __shfl_xor_sync(0xffffffffu, v, off));
                if (tid == 0) red[0] = v;
            }
            __syncthreads();
            if (tid < MM) att[tid] = __expf(att[tid] - red[0]);
            __syncthreads();
            if (tid < 32) {
                float v = att[tid] + att[tid + 32] + att[tid + 64] + att[tid + 96];
                #pragma unroll
                for (int off = 16; off > 0; off >>= 1) v += __shfl_xor_sync(0xffffffffu, v, off);
                if (tid == 0) red[0] = 1.0f / v;
            }
            __syncthreads();
            // x[d] = (sum_m e[m] * mem[m][d]) * (1/sum e)
            if (tid < DD) {
                float acc = 0.f;
                #pragma unroll 8
                for (int m = 0; m < MM; ++m) acc += att[m] * mem[m * MPAD + tid];
                cat[tid] = acc * red[0];
            }
            __syncthreads();
            // fc1 partial: q_new = [x,q] @ w_fc1^T + b_fc1 ; 8 k-splits x 50 float4 cols (K=400)
            if (tid < 400) {
                int ks = tid / 50, c = tid % 50;
                const float4* W4 = reinterpret_cast<const float4*>(g_wTfc1);
                float4 acc = make_float4(0.f, 0.f, 0.f, 0.f);
                int k0 = ks * 50;
                #pragma unroll 5
                for (int k = k0; k < k0 + 50; ++k) {
                    float v = cat[k];
                    float4 w = W4[k * 50 + c];
                    acc.x += v * w.x; acc.y += v * w.y; acc.z += v * w.z; acc.w += v * w.w;
                }
                reinterpret_cast<float4*>(part)[ks * 50 + c] = acc;
            }
            __syncthreads();
            if (tid < DD) {
                float acc = b_fc1[tid];
                #pragma unroll
                for (int ks = 0; ks < 8; ++ks) acc += part[ks * 200 + tid];
                qh[tid] = acc;
                cat[DD + tid] = acc;
            }
            __syncthreads();
        }

        // ---- epilogue: output q, slot update ----
        if (tid < DD) {
            float s = mem[slot * MPAD + tid];
            sv[tid] = s;
            float qv = cat[DD + tid];
            cat[tid] = qv + s;                       // u = q + slot_vec
            out[(b * JJ + j) * DD + tid] = qv;       // emit q
        }
        __syncthreads();
        // z = tanh((q+sv) @ w_fc^T + 2*b_fc) ; mem[slot] = z * sv
        if (tid < 400) {
            int ks = tid / 50, c = tid % 50;
            const float4* W4 = reinterpret_cast<const float4*>(g_wTfc);
            float4 acc = make_float4(0.f, 0.f, 0.f, 0.f);
            int k0 = ks * 25;
            #pragma unroll 5
            for (int k = k0; k < k0 + 25; ++k) {
                float v = cat[k];
                float4 w = W4[k * 50 + c];
                acc.x += v * w.x; acc.y += v * w.y; acc.z += v * w.z; acc.w += v * w.w;
            }
            reinterpret_cast<float4*>(part)[ks * 50 + c] = acc;
        }
        __syncthreads();
        if (tid < DD) {
            float acc = 2.0f * b_fc[tid];
            #pragma unroll
            for (int ks = 0; ks < 8; ++ks) acc += part[ks * 200 + tid];
            mem[slot * MPAD + tid] = tanhf(acc) * sv[tid];
        }
        __syncthreads();
    }
}

extern "C" void kernel_launch(void* const* d_in, const int* in_sizes, int n_in,
                              void* d_out, int out_size)
{
    const float* cosp  = (const float*)d_in[0];
    const float* bank  = (const float*)d_in[1];
    const float* mem_a = (const float*)d_in[2];
    const float* mem_b = (const float*)d_in[3];
    const float* w_fc  = (const float*)d_in[4];
    const float* b_fc  = (const float*)d_in[5];
    const float* w_fc1 = (const float*)d_in[6];
    const float* b_fc1 = (const float*)d_in[7];
    const float* w_ih  = (const float*)d_in[8];
    const float* w_hh  = (const float*)d_in[9];
    const float* b_ih  = (const float*)d_in[10];
    const float* b_hh  = (const float*)d_in[11];
    float* out = (float*)d_out;

    prep_kernel<<<148, 256>>>(w_fc, w_fc1, w_ih, w_hh, b_ih, b_hh);

    size_t smem_bytes = SM_TOTAL_FLOATS * sizeof(float);
    cudaFuncSetAttribute(speaker_kernel, cudaFuncAttributeMaxDynamicSharedMemorySize,
                         (int)smem_bytes);
    speaker_kernel<<<BB, NTHREADS, smem_bytes>>>(cosp, bank, mem_a, mem_b, b_fc, b_fc1, out);
}

// round 3
// speedup vs baseline: 1.8084x; 1.8084x over previous
#include <cuda_runtime.h>
#include <cstdint>

#define BB 32
#define JJ 256
#define MM 128
#define DD 200
#define MPAD 201
#define NTH 512
#define CH 50            // output channels per cluster rank
#define CSZ 4            // cluster size

// ---------------- persistent transposed weight scratch (fp32) ----------------
// g_wTg  : [k=0..399][4*d+g] (k<200 -> w_ih, else w_hh), gate-interleaved: one
//          float4 column = (i,f,g,o) of channel d.
// g_wTfc1: [k=0..399][d]  (k over concat(x,q))
// g_wTfc : [k=0..199][d]
// g_bg   : [800] = b_ih+b_hh gate-interleaved
__device__ __align__(16) float g_wTg[400 * 800];
__device__ __align__(16) float g_wTfc1[400 * 200];
__device__ __align__(16) float g_wTfc[200 * 200];
__device__ __align__(16) float g_bg[800];

__global__ void prep_kernel(const float* __restrict__ w_fc, const float* __restrict__ w_fc1,
                            const float* __restrict__ w_ih, const float* __restrict__ w_hh,
                            const float* __restrict__ b_ih, const float* __restrict__ b_hh)
{
    int stride = gridDim.x * blockDim.x;
    int i0 = blockIdx.x * blockDim.x + threadIdx.x;

    for (int idx = i0; idx < 400 * 800; idx += stride) {
        int k = idx / 800, rem = idx % 800;
        int d = rem >> 2, g = rem & 3;
        int o = g * 200 + d;
        g_wTg[idx] = (k < 200) ? w_ih[o * 200 + k] : w_hh[o * 200 + (k - 200)];
    }
    for (int idx = i0; idx < 800; idx += stride) {
        int d = idx >> 2, g = idx & 3;
        int o = g * 200 + d;
        g_bg[idx] = b_ih[o] + b_hh[o];
    }
    for (int idx = i0; idx < 400 * 200; idx += stride) {
        int k = idx / 200, d = idx % 200;
        g_wTfc1[idx] = w_fc1[d * 400 + k];
    }
    for (int idx = i0; idx < 200 * 200; idx += stride) {
        int k = idx / 200, d = idx % 200;
        g_wTfc[idx] = w_fc[d * 200 + k];
    }
}

__device__ __forceinline__ float sigf(float v) { return 1.0f / (1.0f + __expf(-v)); }

__device__ __forceinline__ void cluster_sync()
{
    asm volatile("barrier.cluster.arrive.aligned;\n\t"
                 "barrier.cluster.wait.aligned;" ::: "memory");
}
__device__ __forceinline__ void st_peer(uint32_t laddr, uint32_t peer, float v)
{
    uint32_t r;
    asm volatile("mapa.shared::cluster.u32 %0, %1, %2;" : "=r"(r) : "r"(laddr), "r"(peer));
    asm volatile("st.shared::cluster.f32 [%0], %1;" :: "r"(r), "f"(v) : "memory");
}

// ---------------- SMEM layout (floats) ----------------
#define SM_MEM 0                       // mem[2][128][201] = 51456
#define SM_H   51456                   // hbuf[2][200]
#define SM_Q   (SM_H + 400)            // qbuf[2][200]
#define SM_X   (SM_Q + 400)            // xv[200]
#define SM_ATT (SM_X + 200)            // att[128]
#define SM_CV  (SM_ATT + 128)          // cvec[64] (50 used, local channels)
#define SM_SV  (SM_CV + 64)            // sv[200]
#define SM_Z   (SM_SV + 200)           // zv[200]
#define SM_CS  (SM_Z + 200)            // cosj[128]
#define SM_BJ  (SM_CS + 128)           // bankj[200]
#define SM_P   (SM_BJ + 200)           // part[1664] (gates: 8x200; fc ops: 8x50; h/x: 2x200; att: 4x128)
#define SM_RED (SM_P + 1664)           // red[8]
#define SM_TOT (SM_RED + 8)            // 55048 floats = 220192 B

__global__ void __launch_bounds__(NTH, 1) __cluster_dims__(CSZ, 1, 1)
speaker_kernel(const float* __restrict__ cosp, const float* __restrict__ bank,
               const float* __restrict__ mem_a, const float* __restrict__ mem_b,
               const float* __restrict__ b_fc, const float* __restrict__ b_fc1,
               float* __restrict__ out)
{
    extern __shared__ float sm[];
    float* smem_mem = sm + SM_MEM;
    float* hbuf = sm + SM_H;
    float* qbuf = sm + SM_Q;
    float* xv   = sm + SM_X;
    float* att  = sm + SM_ATT;
    float* cvec = sm + SM_CV;
    float* sv   = sm + SM_SV;
    float* zv   = sm + SM_Z;
    float* cosj = sm + SM_CS;
    float* bankj= sm + SM_BJ;
    float* part = sm + SM_P;
    float* red  = sm + SM_RED;

    const int tid  = threadIdx.x;
    const int lane = blockIdx.x >> 2;      // batch index
    const uint32_t rank = blockIdx.x & 3;  // cluster rank
    const uint32_t sb = (uint32_t)__cvta_generic_to_shared(sm);

    // load both memory banks (replicated per rank)
    for (int idx = tid; idx < MM * DD; idx += NTH) {
        int m = idx / DD, d = idx % DD;
        smem_mem[m * MPAD + d]              = mem_a[lane * MM * DD + idx];
        smem_mem[MM * MPAD + m * MPAD + d]  = mem_b[lane * MM * DD + idx];
    }
    __syncthreads();

    for (int j = 0; j < JJ; ++j) {
        const int flag = j & 1;
        const int slot = j >> 1;
        float* mem = smem_mem + flag * (MM * MPAD);

        // ---- stage ----
        if (tid < MM) cosj[tid]  = cosp[(lane * JJ + j) * MM + tid];
        if (tid < DD) bankj[tid] = bank[(j * BB + lane) * DD + tid];
        if (tid < CH) cvec[tid] = 0.0f;
        __syncthreads();

        // ---- h init (replicated): h[d] = sum_m cos[m]*mem[m][d], 2-way m-split ----
        if (tid < 400) {
            int d = tid % 200, hf = tid / 200;
            float a = 0.f;
            const float* mp = mem + (hf * 64) * MPAD + d;
            #pragma unroll 8
            for (int m = 0; m < 64; ++m) a += cosj[hf * 64 + m] * mp[m * MPAD];
            part[hf * 200 + d] = a;
        }
        __syncthreads();
        if (tid < DD) hbuf[tid] = part[tid] + part[200 + tid];   // hbuf[0]
        __syncthreads();

        // ---- q init (col-split fp32 fc): rank computes its 50 channels ----
        if (tid < 400) {
            int ks = tid / 50, c = tid % 50;
            float a = 0.f;
            const float* W = g_wTfc + rank * CH + c;
            #pragma unroll 5
            for (int i = 0; i < 25; ++i) {
                int k = ks * 25 + i;
                a += bankj[k] * W[k * 200];
            }
            part[ks * 50 + c] = a;
        }
        __syncthreads();
        if (tid < CH) {
            float a = b_fc[rank * CH + tid];
            #pragma unroll
            for (int ks = 0; ks < 8; ++ks) a += part[ks * 50 + tid];
            int off = SM_Q + rank * CH + tid;       // qbuf[0]
            qbuf[rank * CH + tid] = a;
            #pragma unroll
            for (uint32_t pr = 1; pr < CSZ; ++pr) st_peer(sb + 4u * off, (rank + pr) & 3, a);
        }
        cluster_sync();   // q0 visible everywhere

        // ---------------- inner loop P=3 ----------------
        for (int p = 0; p < 3; ++p) {
            float* qb     = qbuf + (p & 1) * 200;
            float* qb_new = qbuf + ((p + 1) & 1) * 200;
            float* hb_old = hbuf + (p & 1) * 200;
            float* hb_new = hbuf + ((p + 1) & 1) * 200;

            // gates (col-split fp32): rank's 50 channels (float4 = i,f,g,o),
            // 8 k-splits x 50 float4 cols
            if (tid < 400) {
                int ks = tid / 50, c = tid % 50;
                const float4* W4 = reinterpret_cast<const float4*>(g_wTg)
                                   + rank * CH + c;
                const float* act = (ks < 4) ? (qb + ks * 50) : (hb_old + (ks - 4) * 50);
                float4 acc = make_float4(0.f, 0.f, 0.f, 0.f);
                int k0 = ks * 50;
                #pragma unroll 10
                for (int i = 0; i < 50; ++i) {
                    float v = act[i];
                    float4 w = W4[(k0 + i) * 200];
                    acc.x += v * w.x; acc.y += v * w.y; acc.z += v * w.z; acc.w += v * w.w;
                }
                reinterpret_cast<float4*>(part)[ks * 50 + c] = acc;  // part[ks*200 + c*4]
            }
            __syncthreads();
            // combine 8 k-splits + LSTM elementwise via quad shuffle
            {
                float s = 0.f;
                if (tid < 200) {
                    #pragma unroll
                    for (int ks = 0; ks < 8; ++ks) s += part[ks * 200 + tid];
                    s += g_bg[rank * 200 + tid];
                }
                if (tid < 224) {  // 7 full warps for shfl
                    float ig = __shfl_sync(0xffffffffu, s, 0, 4);
                    float fg = __shfl_sync(0xffffffffu, s, 1, 4);
                    float gg = __shfl_sync(0xffffffffu, s, 2, 4);
                    float og = __shfl_sync(0xffffffffu, s, 3, 4);
                    if (tid < 200 && (tid & 3) == 0) {
                        int dl = tid >> 2;
                        float cc = sigf(fg) * cvec[dl] + sigf(ig) * tanhf(gg);
                        cvec[dl] = cc;
                        float hh = sigf(og) * tanhf(cc);
                        int off = SM_H + ((p + 1) & 1) * 200 + rank * CH + dl;
                        hb_new[rank * CH + dl] = hh;
                        #pragma unroll
                        for (uint32_t pr = 1; pr < CSZ; ++pr)
                            st_peer(sb + 4u * off, (rank + pr) & 3, hh);
                    }
                }
            }
            cluster_sync();   // h exchange visible

            // attention logits (replicated, 4-way d-split over 512 threads)
            {
                int m = tid & 127, seg = tid >> 7;
                float a = 0.f;
                const float* mrow = mem + m * MPAD + seg * 50;
                const float* hseg = hb_new + seg * 50;
                #pragma unroll 10
                for (int d = 0; d < 50; ++d) a += hseg[d] * mrow[d];
                part[seg * 128 + m] = a;
            }
            __syncthreads();
            if (tid < MM) att[tid] = part[tid] + part[128 + tid] + part[256 + tid] + part[384 + tid];
            __syncthreads();
            if (tid < 32) {
                float v = fmaxf(fmaxf(att[tid], att[tid + 32]), fmaxf(att[tid + 64], att[tid + 96]));
                #pragma unroll
                for (int o = 16; o > 0; o >>= 1) v = fmaxf(v, __shfl_xor_sync(0xffffffffu, v, o));
                if (tid == 0) red[0] = v;
            }
            __syncthreads();
            if (tid < MM) att[tid] = __expf(att[tid] - red[0]);
            __syncthreads();
            if (tid < 32) {
                float v = att[tid] + att[tid + 32] + att[tid + 64] + att[tid + 96];
                #pragma unroll
                for (int o = 16; o > 0; o >>= 1) v += __shfl_xor_sync(0xffffffffu, v, o);
                if (tid == 0) red[1] = 1.0f / v;
            }
            __syncthreads();
            // x (replicated, 2-way m-split)
            if (tid < 400) {
                int d = tid % 200, hf = tid / 200;
                float a = 0.f;
                const float* mp = mem + (hf * 64) * MPAD + d;
                #pragma unroll 8
                for (int m = 0; m < 64; ++m) a += att[hf * 64 + m] * mp[m * MPAD];
                part[hf * 200 + d] = a;
            }
            __syncthreads();
            if (tid < DD) xv[tid] = (part[tid] + part[200 + tid]) * red[1];
            __syncthreads();

            // fc1 (col-split fp32): rank's 50 channels, 8 k-splits x 50 cols
            if (tid < 400) {
                int ks = tid / 50, c = tid % 50;
                const float* W = g_wTfc1 + rank * CH + c;
                const float* act = (ks < 4) ? (xv + ks * 50) : (qb + (ks - 4) * 50);
                float a = 0.f;
                int k0 = ks * 50;
                #pragma unroll 10
                for (int i = 0; i < 50; ++i) a += act[i] * W[(k0 + i) * 200];
                part[ks * 50 + c] = a;
            }
            __syncthreads();
            if (tid < CH) {
                float a = b_fc1[rank * CH + tid];
                #pragma unroll
                for (int ks = 0; ks < 8; ++ks) a += part[ks * 50 + tid];
                int off = SM_Q + ((p + 1) & 1) * 200 + rank * CH + tid;
                qb_new[rank * CH + tid] = a;
                #pragma unroll
                for (uint32_t pr = 1; pr < CSZ; ++pr) st_peer(sb + 4u * off, (rank + pr) & 3, a);
            }
            cluster_sync();   // q exchange visible
        }

        // ---- epilogue ----
        float* qfin = qbuf + 200;   // qbuf[1] after p=2
        if (tid < DD) sv[tid] = mem[slot * MPAD + tid];
        if (tid < CH) out[(lane * JJ + j) * DD + rank * CH + tid] = qfin[rank * CH + tid];
        __syncthreads();
        // z = tanh((q+sv) @ w_fc^T + 2*b_fc) (col-split fp32)
        if (tid < 400) {
            int ks = tid / 50, c = tid % 50;
            float a = 0.f;
            const float* W = g_wTfc + rank * CH + c;
            #pragma unroll 5
            for (int i = 0; i < 25; ++i) {
                int k = ks * 25 + i;
                a += (qfin[k] + sv[k]) * W[k * 200];
            }
            part[ks * 50 + c] = a;
        }
        __syncthreads();
        if (tid < CH) {
            float a = 2.0f * b_fc[rank * CH + tid];
            #pragma unroll
            for (int ks = 0; ks < 8; ++ks) a += part[ks * 50 + tid];
            float zz = tanhf(a);
            int off = SM_Z + rank * CH + tid;
            zv[rank * CH + tid] = zz;
            #pragma unroll
            for (uint32_t pr = 1; pr < CSZ; ++pr) st_peer(sb + 4u * off, (rank + pr) & 3, zz);
        }
        cluster_sync();   // z visible
        if (tid < DD) mem[slot * MPAD + tid] = zv[tid] * sv[tid];
        __syncthreads();
    }
}

extern "C" void kernel_launch(void* const* d_in, const int* in_sizes, int n_in,
                              void* d_out, int out_size)
{
    const float* cosp  = (const float*)d_in[0];
    const float* bank  = (const float*)d_in[1];
    const float* mem_a = (const float*)d_in[2];
    const float* mem_b = (const float*)d_in[3];
    const float* w_fc  = (const float*)d_in[4];
    const float* b_fc  = (const float*)d_in[5];
    const float* w_fc1 = (const float*)d_in[6];
    const float* b_fc1 = (const float*)d_in[7];
    const float* w_ih  = (const float*)d_in[8];
    const float* w_hh  = (const float*)d_in[9];
    const float* b_ih  = (const float*)d_in[10];
    const float* b_hh  = (const float*)d_in[11];
    float* out = (float*)d_out;

    prep_kernel<<<148, 256>>>(w_fc, w_fc1, w_ih, w_hh, b_ih, b_hh);

    size_t smem_bytes = SM_TOT * sizeof(float);
    cudaFuncSetAttribute(speaker_kernel, cudaFuncAttributeMaxDynamicSharedMemorySize,
                         (int)smem_bytes);
    speaker_kernel<<<BB * CSZ, NTH, smem_bytes>>>(cosp, bank, mem_a, mem_b, b_fc, b_fc1, out);
}

// round 4
// speedup vs baseline: 2.2744x; 1.2577x over previous
#include <cuda_runtime.h>
#include <cstdint>

#define BB 32
#define JJ 256
#define MM 128
#define DD 200
#define NTH 512
#define CH 50            // d-chunk per rank
#define CSZ 4            // cluster size
#define MP 53            // padded mem chunk row stride (53 mod 32 = 21, coprime -> conflict-free)

// ---------------- persistent transposed weight scratch (fp32) ----------------
// g_wTg  : [k=0..399][4*d+g] (k<200 -> w_ih, else w_hh); float4 per channel = (i,f,g,o)
// g_wTfc1: [k=0..399][d]     (k<200 -> x, else q)
// g_wTfc : [k=0..199][d]
// g_bg   : [800] = b_ih+b_hh gate-interleaved (d*4+g)
__device__ __align__(16) float g_wTg[400 * 800];
__device__ __align__(16) float g_wTfc1[400 * 200];
__device__ __align__(16) float g_wTfc[200 * 200];
__device__ __align__(16) float g_bg[800];

__global__ void prep_kernel(const float* __restrict__ w_fc, const float* __restrict__ w_fc1,
                            const float* __restrict__ w_ih, const float* __restrict__ w_hh,
                            const float* __restrict__ b_ih, const float* __restrict__ b_hh)
{
    int stride = gridDim.x * blockDim.x;
    int i0 = blockIdx.x * blockDim.x + threadIdx.x;

    for (int idx = i0; idx < 400 * 800; idx += stride) {
        int k = idx / 800, rem = idx % 800;
        int d = rem >> 2, g = rem & 3;
        int o = g * 200 + d;
        g_wTg[idx] = (k < 200) ? w_ih[o * 200 + k] : w_hh[o * 200 + (k - 200)];
    }
    for (int idx = i0; idx < 800; idx += stride) {
        int d = idx >> 2, g = idx & 3;
        int o = g * 200 + d;
        g_bg[idx] = b_ih[o] + b_hh[o];
    }
    for (int idx = i0; idx < 400 * 200; idx += stride) {
        int k = idx / 200, d = idx % 200;
        g_wTfc1[idx] = w_fc1[d * 400 + k];
    }
    for (int idx = i0; idx < 200 * 200; idx += stride) {
        int k = idx / 200, d = idx % 200;
        g_wTfc[idx] = w_fc[d * 200 + k];
    }
}

__device__ __forceinline__ float sigf(float v) { return 1.0f / (1.0f + __expf(-v)); }
// fast tanh for within-step paths (h/c reset every j; err ~1e-7)
__device__ __forceinline__ float ftanh(float x) { return 1.0f - 2.0f / (__expf(2.0f * x) + 1.0f); }

__device__ __forceinline__ void cluster_bar()
{
    asm volatile("barrier.cluster.arrive.aligned;\n\t"
                 "barrier.cluster.wait.aligned;" ::: "memory");
}
__device__ __forceinline__ void st_peer(uint32_t laddr, uint32_t peer, float v)
{
    uint32_t r;
    asm volatile("mapa.shared::cluster.u32 %0, %1, %2;" : "=r"(r) : "r"(laddr), "r"(peer));
    asm volatile("st.shared::cluster.f32 [%0], %1;" :: "r"(r), "f"(v) : "memory");
}
__device__ __forceinline__ void st_peer_v4(uint32_t laddr, uint32_t peer, float4 v)
{
    uint32_t r;
    unsigned long long lo = (unsigned long long)__float_as_uint(v.x) |
                            ((unsigned long long)__float_as_uint(v.y) << 32);
    unsigned long long hi = (unsigned long long)__float_as_uint(v.z) |
                            ((unsigned long long)__float_as_uint(v.w) << 32);
    asm volatile("mapa.shared::cluster.u32 %0, %1, %2;" : "=r"(r) : "r"(laddr), "r"(peer));
    asm volatile("st.shared::cluster.b64 [%0], %1;" :: "r"(r), "l"(lo) : "memory");
    asm volatile("st.shared::cluster.b64 [%0+8], %1;" :: "r"(r), "l"(hi) : "memory");
}

// ---------------- SMEM layout (float indices) ----------------
#define SM_MEM   0                      // mem[2][128][MP] chunk = 13568
#define SM_GP    13568                  // gparts[4 src][50 quads]*4 = 800 (16B aligned)
#define SM_ATTP  14368                  // attp[4][128] = 512
#define SM_QP    14880                  // qparts[4][50] = 200
#define SM_ZP    15080                  // zparts[4][50] = 200
#define SM_PART  15280                  // part scratch (1600, 16B aligned)
#define SM_ATT   16880                  // att[128]
#define SM_RED   17008                  // red[8]
#define SM_XV    17016                  // xv[56]
#define SM_CS    17072                  // cosj[128]
#define SM_BJ    17200                  // bankj[200]
#define SM_QL    17400                  // qloc[56]
#define SM_HL    17456                  // hloc[56]
#define SM_CV    17512                  // cvec[56]
#define SM_BG    17568                  // bgs[224] (padded for clamp-free warp access)
#define SM_BFC   17792                  // bfcs[56]
#define SM_BFC1  17848                  // bfc1s[56]
#define SM_TOT   17904                  // 71616 bytes

__global__ void __launch_bounds__(NTH, 1) __cluster_dims__(CSZ, 1, 1)
speaker_kernel(const float* __restrict__ cosp, const float* __restrict__ bank,
               const float* __restrict__ mem_a, const float* __restrict__ mem_b,
               const float* __restrict__ b_fc, const float* __restrict__ b_fc1,
               float* __restrict__ out)
{
    extern __shared__ float sm[];
    float* smem_mem = sm + SM_MEM;
    float* gparts = sm + SM_GP;
    float* attp   = sm + SM_ATTP;
    float* qparts = sm + SM_QP;
    float* zparts = sm + SM_ZP;
    float* part   = sm + SM_PART;
    float* att    = sm + SM_ATT;
    float* red    = sm + SM_RED;
    float* xv     = sm + SM_XV;
    float* cosj   = sm + SM_CS;
    float* bankj  = sm + SM_BJ;
    float* qloc   = sm + SM_QL;
    float* hloc   = sm + SM_HL;
    float* cvec   = sm + SM_CV;
    float* bgs    = sm + SM_BG;
    float* bfcs   = sm + SM_BFC;
    float* bfc1s  = sm + SM_BFC1;

    const int tid  = threadIdx.x;
    const int lane = blockIdx.x >> 2;        // batch index
    const uint32_t rank = blockIdx.x & 3;    // cluster rank (owns d-chunk [50r, 50r+50))
    const int cbase = (int)rank * CH;        // global d-chunk base
    const uint32_t sb = (uint32_t)__cvta_generic_to_shared(sm);

    // ---- stage biases for this rank's chunk; load mem d-chunks ----
    if (tid < 224) bgs[tid] = g_bg[rank * 200 + min(tid, 199)];
    if (tid < CH) { bfcs[tid] = b_fc[cbase + tid]; bfc1s[tid] = b_fc1[cbase + tid]; }
    for (int idx = tid; idx < MM * CH; idx += NTH) {
        int m = idx / CH, d = idx % CH;
        smem_mem[m * MP + d]             = mem_a[lane * MM * DD + m * DD + cbase + d];
        smem_mem[MM * MP + m * MP + d]   = mem_b[lane * MM * DD + m * DD + cbase + d];
    }
    __syncthreads();

    for (int j = 0; j < JJ; ++j) {
        const int flag = j & 1;
        const int slot = j >> 1;
        float* mem = smem_mem + flag * (MM * MP);

        // ---- stage cos/bank, reset c ----
        if (tid < MM) cosj[tid]  = cosp[(lane * JJ + j) * MM + tid];
        if (tid < DD) bankj[tid] = bank[(j * BB + lane) * DD + tid];
        if (tid < CH) cvec[tid] = 0.0f;
        __syncthreads();

        // ---- P1: q-init partials (col-split, full k) + h-init chunk partials ----
        if (tid < 400) {          // q: 8 ks x 50 cols, 25 iters
            int ks = tid / 50, c = tid % 50;
            int k0 = ks * 25;
            float a = 0.f;
            const float* W = g_wTfc + cbase + c;
            #pragma unroll 5
            for (int i = 0; i < 25; ++i) a += bankj[k0 + i] * W[(k0 + i) * 200];
            part[ks * 50 + c] = a;
        } else if (tid < 500) {   // h chunk: 2 m-segs x 50 d, 64 iters
            int t = tid - 400, seg = t / 50, d = t % 50;
            float a = 0.f;
            const float* mp = mem + (seg * 64) * MP + d;
            #pragma unroll 8
            for (int m = 0; m < 64; ++m) a += cosj[seg * 64 + m] * mp[m * MP];
            part[400 + seg * 50 + d] = a;
        }
        __syncthreads();
        // ---- P2: combine q (local chunk) + combine h (local chunk). No barrier. ----
        if (tid < CH) {
            float a = bfcs[tid];
            #pragma unroll
            for (int ks = 0; ks < 8; ++ks) a += part[ks * 50 + tid];
            qloc[tid] = a;
        } else if (tid >= 64 && tid < 64 + CH) {
            int t = tid - 64;
            hloc[t] = part[400 + t] + part[450 + t];
        }
        __syncthreads();

        // ---------------- inner loop P=3 ----------------
        for (int p = 0; p < 3; ++p) {
            // G0: gates partials, k-local (rank's q-chunk + h-chunk), all 800 outputs
            if (tid < 400) {
                int ks = tid / 200, c = tid % 200;
                const float4* W4 = reinterpret_cast<const float4*>(g_wTg)
                                   + (ks ? (200 + cbase) : cbase) * 200 + c;
                const float* act = ks ? hloc : qloc;
                float4 acc = make_float4(0.f, 0.f, 0.f, 0.f);
                #pragma unroll 10
                for (int i = 0; i < CH; ++i) {
                    float v = act[i];
                    float4 w = W4[i * 200];
                    acc.x += v * w.x; acc.y += v * w.y; acc.z += v * w.z; acc.w += v * w.w;
                }
                reinterpret_cast<float4*>(part)[ks * 200 + c] = acc;
            }
            __syncthreads();
            // G0b: combine 2 k-splits, deposit quad to owning rank
            if (tid < 200) {
                const float4* p4 = reinterpret_cast<const float4*>(part);
                float4 a = p4[tid], b = p4[200 + tid];
                float4 v = make_float4(a.x + b.x, a.y + b.y, a.z + b.z, a.w + b.w);
                int owner = tid / CH, cq = tid % CH;
                uint32_t off = SM_GP + rank * 200 + cq * 4;
                if (owner == (int)rank) *reinterpret_cast<float4*>(sm + off) = v;
                else st_peer_v4(sb + 4u * off, (uint32_t)owner, v);
            }
            cluster_bar();   // Bg: gate partials delivered
            // G1: reduce 4 partials + LSTM (quad-parallel activations)
            if (tid < 224) {
                int t = min(tid, 199);
                int chl = t >> 2, gi = t & 3;
                float g = bgs[t];
                #pragma unroll
                for (int s = 0; s < 4; ++s) g += gparts[s * 200 + chl * 4 + gi];
                float val = (gi == 2) ? ftanh(g) : sigf(g);
                float ig = __shfl_sync(0xffffffffu, val, 0, 4);
                float fg = __shfl_sync(0xffffffffu, val, 1, 4);
                float gg = __shfl_sync(0xffffffffu, val, 2, 4);
                float og = __shfl_sync(0xffffffffu, val, 3, 4);
                if (tid < 200 && gi == 0) {
                    float cc = fg * cvec[chl] + ig * gg;
                    cvec[chl] = cc;
                    hloc[chl] = og * ftanh(cc);
                }
            }
            __syncthreads();
            // G2: attention logit partials over local d-chunk
            if (tid < 256) {
                int m = tid & 127, hf = tid >> 7;
                float a = 0.f;
                const float* mrow = mem + m * MP + hf * 25;
                const float* hseg = hloc + hf * 25;
                #pragma unroll 5
                for (int i = 0; i < 25; ++i) a += hseg[i] * mrow[i];
                part[hf * 128 + m] = a;
            }
            __syncthreads();
            // G2b: push logit partials to all ranks
            if (tid < 128) {
                float a = part[tid] + part[128 + tid];
                uint32_t off = SM_ATTP + rank * 128 + tid;
                sm[off] = a;
                #pragma unroll
                for (uint32_t pr = 1; pr < CSZ; ++pr) st_peer(sb + 4u * off, (rank + pr) & 3, a);
            }
            cluster_bar();   // Ba: att partials delivered
            // G3: combine + warp max
            if (tid < 128) {
                float a = attp[tid] + attp[128 + tid] + attp[256 + tid] + attp[384 + tid];
                att[tid] = a;
                #pragma unroll
                for (int o = 16; o > 0; o >>= 1) a = fmaxf(a, __shfl_xor_sync(0xffffffffu, a, o));
                if ((tid & 31) == 0) red[tid >> 5] = a;
            }
            __syncthreads();
            // G4: exp + warp sum
            if (tid < 128) {
                float gm = fmaxf(fmaxf(red[0], red[1]), fmaxf(red[2], red[3]));
                float e = __expf(att[tid] - gm);
                att[tid] = e;
                #pragma unroll
                for (int o = 16; o > 0; o >>= 1) e += __shfl_xor_sync(0xffffffffu, e, o);
                if ((tid & 31) == 0) red[4 + (tid >> 5)] = e;
            }
            __syncthreads();
            // G5: x chunk partials (8 m-segs x 50 d, 16 iters)
            if (tid < 400) {
                int seg = tid / 50, d = tid % 50;
                float a = 0.f;
                const float* mp = mem + (seg * 16) * MP + d;
                #pragma unroll 8
                for (int m = 0; m < 16; ++m) a += att[seg * 16 + m] * mp[m * MP];
                part[seg * 50 + d] = a;
            }
            __syncthreads();
            // G5b: xv = normalized x chunk
            if (tid < CH) {
                float inv = 1.0f / (red[4] + red[5] + red[6] + red[7]);
                float a = 0.f;
                #pragma unroll
                for (int s = 0; s < 8; ++s) a += part[s * 50 + tid];
                xv[tid] = a * inv;
            }
            __syncthreads();
            // G6: fc1 partials, k-local (x-chunk + q-chunk), all 200 outputs
            if (tid < 400) {
                int ks = tid / 200, c = tid % 200;
                const float* W = g_wTfc1 + (ks ? (200 + cbase) : cbase) * 200 + c;
                const float* act = ks ? qloc : xv;
                float a = 0.f;
                #pragma unroll 10
                for (int i = 0; i < CH; ++i) a += act[i] * W[i * 200];
                part[ks * 200 + c] = a;
            }
            __syncthreads();
            // G6b: deposit q partials to owner
            if (tid < 200) {
                float v = part[tid] + part[200 + tid];
                int owner = tid / CH;
                uint32_t off = SM_QP + rank * CH + (tid % CH);
                if (owner == (int)rank) sm[off] = v;
                else st_peer(sb + 4u * off, (uint32_t)owner, v);
            }
            cluster_bar();   // Bq: q partials delivered
            // G7: q chunk reduce
            if (tid < CH) {
                float a = bfc1s[tid];
                #pragma unroll
                for (int s = 0; s < 4; ++s) a += qparts[s * CH + tid];
                qloc[tid] = a;
            }
            __syncthreads();
        }

        // ---- epilogue: z partials (k-local over q-chunk + sv-chunk) + out write ----
        if (tid < 400) {
            int ks = tid / 200, c = tid % 200;
            const float* W = g_wTfc + (cbase + ks * 25) * 200 + c;
            const float* svp = mem + slot * MP + ks * 25;
            const float* qp  = qloc + ks * 25;
            float a = 0.f;
            #pragma unroll 5
            for (int i = 0; i < 25; ++i) a += (qp[i] + svp[i]) * W[i * 200];
            part[ks * 200 + c] = a;
        } else if (tid >= 448 && tid < 448 + CH) {
            int t = tid - 448;
            out[(lane * JJ + j) * DD + cbase + t] = qloc[t];
        }
        __syncthreads();
        if (tid < 200) {
            float v = part[tid] + part[200 + tid];
            int owner = tid / CH;
            uint32_t off = SM_ZP + rank * CH + (tid % CH);
            if (owner == (int)rank) sm[off] = v;
            else st_peer(sb + 4u * off, (uint32_t)owner, v);
        }
        cluster_bar();   // Bz: z partials delivered
        if (tid < CH) {
            float a = 2.0f * bfcs[tid];
            #pragma unroll
            for (int s = 0; s < 4; ++s) a += zparts[s * CH + tid];
            float z = tanhf(a);                 // libm tanh on the mem-recurrence path
            mem[slot * MP + tid] *= z;          // local-only update (mem is d-split)
        }
        __syncthreads();
    }
}

extern "C" void kernel_launch(void* const* d_in, const int* in_sizes, int n_in,
                              void* d_out, int out_size)
{
    const float* cosp  = (const float*)d_in[0];
    const float* bank  = (const float*)d_in[1];
    const float* mem_a = (const float*)d_in[2];
    const float* mem_b = (const float*)d_in[3];
    const float* w_fc  = (const float*)d_in[4];
    const float* b_fc  = (const float*)d_in[5];
    const float* w_fc1 = (const float*)d_in[6];
    const float* b_fc1 = (const float*)d_in[7];
    const float* w_ih  = (const float*)d_in[8];
    const float* w_hh  = (const float*)d_in[9];
    const float* b_ih  = (const float*)d_in[10];
    const float* b_hh  = (const float*)d_in[11];
    float* out = (float*)d_out;

    prep_kernel<<<148, 256>>>(w_fc, w_fc1, w_ih, w_hh, b_ih, b_hh);

    size_t smem_bytes = SM_TOT * sizeof(float);
    cudaFuncSetAttribute(speaker_kernel, cudaFuncAttributeMaxDynamicSharedMemorySize,
                         (int)smem_bytes);
    speaker_kernel<<<BB * CSZ, NTH, smem_bytes>>>(cosp, bank, mem_a, mem_b, b_fc, b_fc1, out);
}